// round 5
// baseline (speedup 1.0000x reference)
#include <cuda_runtime.h>
#include <cuda_bf16.h>
#include <math.h>

#define PMAX 512
#define IMG_H 256
#define IMG_W 256
#define TANFOV 0.5f
#define FXC (IMG_W / (2.0f * TANFOV))
#define FYC (IMG_H / (2.0f * TANFOV))
#define SH_C0 0.28209479177387814f

// ---- per-gaussian unsorted state ----
__device__ float g_mx[PMAX], g_my[PMAX];
__device__ float g_A[PMAX], g_B[PMAX], g_C[PMAX];
__device__ float g_op[PMAX], g_tpow[PMAX];
__device__ float g_cr[PMAX], g_cg[PMAX], g_cb[PMAX];
__device__ float g_key[PMAX];
__device__ int   g_radii[PMAX];

// ---- sorted, packed for the raster loop ----
__device__ float4 g_s0[PMAX];  // mx, my, A, B
__device__ float4 g_s1[PMAX];  // C, op, tpow, (unused)
__device__ float4 g_s2[PMAX];  // cr, cg, cb, (unused)

__global__ void preprocess_kernel(const float* __restrict__ points,
                                  const float* __restrict__ scales,
                                  const float* __restrict__ rots,
                                  const float* __restrict__ opacities,
                                  const float* __restrict__ shs,
                                  const float* __restrict__ vm,
                                  int P)
{
    int i = blockIdx.x * blockDim.x + threadIdx.x;
    if (i >= PMAX) return;
    const float INF = __int_as_float(0x7f800000);
    if (i >= P) {
        g_key[i] = INF; g_op[i] = 0.0f; g_tpow[i] = INF;
        g_mx[i] = 0.f; g_my[i] = 0.f; g_A[i] = 0.f; g_B[i] = 0.f; g_C[i] = 0.f;
        g_cr[i] = 0.f; g_cg[i] = 0.f; g_cb[i] = 0.f; g_radii[i] = 0;
        return;
    }

    // scales -> s = exp
    float s0 = __expf(scales[3*i+0]);
    float s1 = __expf(scales[3*i+1]);
    float s2 = __expf(scales[3*i+2]);

    // quat normalize -> R
    float qr = rots[4*i+0], qx = rots[4*i+1], qy = rots[4*i+2], qz = rots[4*i+3];
    float qn = rsqrtf(qr*qr + qx*qx + qy*qy + qz*qz);
    qr *= qn; qx *= qn; qy *= qn; qz *= qn;
    float R00 = 1.f - 2.f*(qy*qy + qz*qz), R01 = 2.f*(qx*qy - qr*qz), R02 = 2.f*(qx*qz + qr*qy);
    float R10 = 2.f*(qx*qy + qr*qz), R11 = 1.f - 2.f*(qx*qx + qz*qz), R12 = 2.f*(qy*qz - qr*qx);
    float R20 = 2.f*(qx*qz - qr*qy), R21 = 2.f*(qy*qz + qr*qx), R22 = 1.f - 2.f*(qx*qx + qy*qy);

    // M = R * diag(s)
    float M00 = R00*s0, M01 = R01*s1, M02 = R02*s2;
    float M10 = R10*s0, M11 = R11*s1, M12 = R12*s2;
    float M20 = R20*s0, M21 = R21*s1, M22 = R22*s2;

    // Sigma = M M^T (symmetric)
    float S00 = M00*M00 + M01*M01 + M02*M02;
    float S01 = M00*M10 + M01*M11 + M02*M12;
    float S02 = M00*M20 + M01*M21 + M02*M22;
    float S11 = M10*M10 + M11*M11 + M12*M12;
    float S12 = M10*M20 + M11*M21 + M12*M22;
    float S22 = M20*M20 + M21*M21 + M22*M22;

    // view transform (viewmat row-major 4x4)
    float W00 = vm[0], W01 = vm[1], W02 = vm[2],  T0 = vm[3];
    float W10 = vm[4], W11 = vm[5], W12 = vm[6],  T1 = vm[7];
    float W20 = vm[8], W21 = vm[9], W22 = vm[10], T2 = vm[11];
    float px = points[3*i+0], py = points[3*i+1], pz = points[3*i+2];
    float tx = W00*px + W01*py + W02*pz + T0;
    float ty = W10*px + W11*py + W12*pz + T1;
    float tz = W20*px + W21*py + W22*pz + T2;

    bool visible = tz > 0.2f;
    float tzs = visible ? tz : 1.0f;

    const float lim = 1.3f * TANFOV;
    float txtz = fminf(fmaxf(tx/tzs, -lim), lim) * tzs;
    float tytz = fminf(fmaxf(ty/tzs, -lim), lim) * tzs;

    float inv_z = 1.0f / tzs;
    float inv_z2 = inv_z * inv_z;
    // J (2x3)
    float J00 = FXC * inv_z, J02 = -FXC * txtz * inv_z2;
    float J11 = FYC * inv_z, J12 = -FYC * tytz * inv_z2;

    // Tm = J @ Wrot  (2x3)
    float Tm00 = J00*W00 + J02*W20;
    float Tm01 = J00*W01 + J02*W21;
    float Tm02 = J00*W02 + J02*W22;
    float Tm10 = J11*W10 + J12*W20;
    float Tm11 = J11*W11 + J12*W21;
    float Tm12 = J11*W12 + J12*W22;

    // cov = Tm Sigma Tm^T
    float v00 = S00*Tm00 + S01*Tm01 + S02*Tm02;
    float v01 = S01*Tm00 + S11*Tm01 + S12*Tm02;
    float v02 = S02*Tm00 + S12*Tm01 + S22*Tm02;
    float v10 = S00*Tm10 + S01*Tm11 + S02*Tm12;
    float v11 = S01*Tm10 + S11*Tm11 + S12*Tm12;
    float v12 = S02*Tm10 + S12*Tm11 + S22*Tm12;
    float cov00 = Tm00*v00 + Tm01*v01 + Tm02*v02;
    float cov01 = Tm10*v00 + Tm11*v01 + Tm12*v02;
    float cov11 = Tm10*v10 + Tm11*v11 + Tm12*v12;

    float det_orig = cov00*cov11 - cov01*cov01;
    float a = cov00 + 0.3f;
    float c = cov11 + 0.3f;
    float b = cov01;
    float det = a*c - b*b;
    visible = visible && (det > 0.0f);
    float dets = (det > 0.0f) ? det : 1.0f;
    float comp = sqrtf(fmaxf(det_orig / dets, 0.0f));

    float opac = 1.0f / (1.0f + __expf(-opacities[i]));
    float op_eff = opac * comp * (visible ? 1.0f : 0.0f);

    float inv_det = 1.0f / dets;
    float conA = c * inv_det, conB = -b * inv_det, conC = a * inv_det;

    float mid = 0.5f * (a + c);
    float lam = mid + sqrtf(fmaxf(mid*mid - det, 0.1f));
    int radii = visible ? (int)ceilf(3.0f * sqrtf(lam)) : 0;

    float mx = FXC * tx / tzs + (IMG_W - 1) * 0.5f;
    float my = FYC * ty / tzs + (IMG_H - 1) * 0.5f;

    float cr = fmaxf(shs[3*i+0] * SH_C0 + 0.5f, 0.0f);
    float cg = fmaxf(shs[3*i+1] * SH_C0 + 0.5f, 0.0f);
    float cb = fmaxf(shs[3*i+2] * SH_C0 + 0.5f, 0.0f);

    // log-space skip threshold: if power < tpow then op*exp(power) < 1/255 guaranteed.
    // margin 0.01 covers __expf/__logf rounding so exact checks stay authoritative.
    float tpow;
    if (op_eff > 0.0f) tpow = -__logf(255.0f * op_eff) - 0.01f;
    else               tpow = INF;  // never passes -> always skipped

    g_mx[i] = mx; g_my[i] = my;
    g_A[i] = conA; g_B[i] = conB; g_C[i] = conC;
    g_op[i] = op_eff; g_tpow[i] = tpow;
    g_cr[i] = cr; g_cg[i] = cg; g_cb[i] = cb;
    g_key[i] = visible ? tz : INF;
    g_radii[i] = radii;
}

// Stable rank sort (matches jnp.argsort stable semantics), plus tail outputs.
__global__ void sort_kernel(float* __restrict__ d_out, int out_size, int P)
{
    __shared__ float keys[PMAX];
    int i = threadIdx.x;
    keys[i] = g_key[i];
    __syncthreads();
    float ki = keys[i];
    int rank = 0;
    #pragma unroll 8
    for (int j = 0; j < PMAX; j++) {
        float kj = keys[j];
        rank += (kj < ki) || (kj == ki && j < i);
    }
    g_s0[rank] = make_float4(g_mx[i], g_my[i], g_A[i], g_B[i]);
    g_s1[rank] = make_float4(g_C[i], g_op[i], g_tpow[i], 0.0f);
    g_s2[rank] = make_float4(g_cr[i], g_cg[i], g_cb[i], 0.0f);

    // tail outputs: viewspace_points (zeros) and radii (original order)
    const int rgb_n = 3 * IMG_H * IMG_W;
    if (out_size >= rgb_n + 4 * PMAX) {
        d_out[rgb_n + 3*i + 0] = 0.0f;
        d_out[rgb_n + 3*i + 1] = 0.0f;
        d_out[rgb_n + 3*i + 2] = 0.0f;
        d_out[rgb_n + 3*PMAX + i] = (float)g_radii[i];
    }
}

__global__ void __launch_bounds__(256) raster_kernel(float* __restrict__ out)
{
    __shared__ float4 s0[PMAX];
    __shared__ float4 s1[PMAX];
    __shared__ float4 s2[PMAX];
    int t = threadIdx.x;
    #pragma unroll
    for (int i = t; i < PMAX; i += 256) {
        s0[i] = g_s0[i];
        s1[i] = g_s1[i];
        s2[i] = g_s2[i];
    }
    __syncthreads();

    int px = blockIdx.x * 16 + (t & 15);
    int py = blockIdx.y * 16 + (t >> 4);
    float fx = (float)px;
    float fy = (float)py;

    float T = 1.0f;
    float cr = 0.0f, cg = 0.0f, cb = 0.0f;

    for (int i = 0; i < PMAX; i++) {
        float4 a = s0[i];
        float4 b = s1[i];
        float dx = fx - a.x;
        float dy = fy - a.y;
        // power = -0.5*(A dx^2 + C dy^2) - B dx dy
        float power = fmaf(-0.5f * a.z, dx * dx, fmaf(-0.5f * b.x, dy * dy, -a.w * dx * dy));
        if (power > 0.0f || power < b.z) continue;  // b.z = tpow (log-space alpha cutoff)
        float alpha = fminf(0.99f, b.y * __expf(power));
        if (alpha < 0.003921569f) continue;          // 1/255 (float)
        float w = alpha * T;
        float4 c = s2[i];
        cr = fmaf(w, c.x, cr);
        cg = fmaf(w, c.y, cg);
        cb = fmaf(w, c.z, cb);
        T *= (1.0f - alpha);
        if (T < 1e-4f) break;                        // Texcl monotone nonincreasing
    }

    int idx = py * IMG_W + px;
    out[idx]                     = cr;
    out[IMG_H * IMG_W + idx]     = cg;
    out[2 * IMG_H * IMG_W + idx] = cb;
}

extern "C" void kernel_launch(void* const* d_in, const int* in_sizes, int n_in,
                              void* d_out, int out_size)
{
    const float* points    = (const float*)d_in[0];
    const float* scales    = (const float*)d_in[1];
    const float* rots      = (const float*)d_in[2];
    const float* opacities = (const float*)d_in[3];
    const float* shs       = (const float*)d_in[4];
    const float* viewmat   = (const float*)d_in[5];
    float* out = (float*)d_out;

    int P = in_sizes[0] / 3;
    if (P > PMAX) P = PMAX;

    preprocess_kernel<<<1, PMAX>>>(points, scales, rots, opacities, shs, viewmat, P);
    sort_kernel<<<1, PMAX>>>(out, out_size, P);
    raster_kernel<<<dim3(IMG_W / 16, IMG_H / 16), 256>>>(out);
}

// round 12
// speedup vs baseline: 1.9796x; 1.9796x over previous
#include <cuda_runtime.h>
#include <cuda_bf16.h>
#include <math.h>

#define PMAX 512
#define IMG_H 256
#define IMG_W 256
#define TANFOV 0.5f
#define FXC (IMG_W / (2.0f * TANFOV))
#define FYC (IMG_H / (2.0f * TANFOV))
#define SH_C0 0.28209479177387814f

// ---- sorted, packed for the raster loop ----
// s0: mx, my, -0.5*conA, -conB
// s1: -0.5*conC, op_eff, tpow, ex   (bbox half-extent in x)
// s2: cr, cg, cb, ey                (bbox half-extent in y)
__device__ float4 g_s0[PMAX];
__device__ float4 g_s1[PMAX];
__device__ float4 g_s2[PMAX];

__global__ void __launch_bounds__(PMAX) prep_sort_kernel(
    const float* __restrict__ points,
    const float* __restrict__ scales,
    const float* __restrict__ rots,
    const float* __restrict__ opacities,
    const float* __restrict__ shs,
    const float* __restrict__ vm,
    float* __restrict__ d_out, int out_size, int P)
{
    const float INF = __int_as_float(0x7f800000);
    int i = threadIdx.x;

    float mx = 0.f, my = 0.f, Ah = 0.f, Bh = 0.f, Ch = 0.f;
    float op_eff = 0.f, tpow = INF, ex = 0.f, ey = 0.f;
    float cr = 0.f, cg = 0.f, cb = 0.f;
    float key = INF;
    int   radii = 0;

    if (i < P) {
        // scales -> s = exp
        float s0 = __expf(scales[3*i+0]);
        float s1 = __expf(scales[3*i+1]);
        float s2 = __expf(scales[3*i+2]);

        // quat normalize -> R
        float qr = rots[4*i+0], qx = rots[4*i+1], qy = rots[4*i+2], qz = rots[4*i+3];
        float qn = rsqrtf(qr*qr + qx*qx + qy*qy + qz*qz);
        qr *= qn; qx *= qn; qy *= qn; qz *= qn;
        float R00 = 1.f - 2.f*(qy*qy + qz*qz), R01 = 2.f*(qx*qy - qr*qz), R02 = 2.f*(qx*qz + qr*qy);
        float R10 = 2.f*(qx*qy + qr*qz), R11 = 1.f - 2.f*(qx*qx + qz*qz), R12 = 2.f*(qy*qz - qr*qx);
        float R20 = 2.f*(qx*qz - qr*qy), R21 = 2.f*(qy*qz + qr*qx), R22 = 1.f - 2.f*(qx*qx + qy*qy);

        // M = R * diag(s)
        float M00 = R00*s0, M01 = R01*s1, M02 = R02*s2;
        float M10 = R10*s0, M11 = R11*s1, M12 = R12*s2;
        float M20 = R20*s0, M21 = R21*s1, M22 = R22*s2;

        // Sigma = M M^T
        float S00 = M00*M00 + M01*M01 + M02*M02;
        float S01 = M00*M10 + M01*M11 + M02*M12;
        float S02 = M00*M20 + M01*M21 + M02*M22;
        float S11 = M10*M10 + M11*M11 + M12*M12;
        float S12 = M10*M20 + M11*M21 + M12*M22;
        float S22 = M20*M20 + M21*M21 + M22*M22;

        float W00 = vm[0], W01 = vm[1], W02 = vm[2],  T0 = vm[3];
        float W10 = vm[4], W11 = vm[5], W12 = vm[6],  T1 = vm[7];
        float W20 = vm[8], W21 = vm[9], W22 = vm[10], T2 = vm[11];
        float px = points[3*i+0], py = points[3*i+1], pz = points[3*i+2];
        float tx = W00*px + W01*py + W02*pz + T0;
        float ty = W10*px + W11*py + W12*pz + T1;
        float tz = W20*px + W21*py + W22*pz + T2;

        bool visible = tz > 0.2f;
        float tzs = visible ? tz : 1.0f;

        const float lim = 1.3f * TANFOV;
        float txtz = fminf(fmaxf(tx/tzs, -lim), lim) * tzs;
        float tytz = fminf(fmaxf(ty/tzs, -lim), lim) * tzs;

        float inv_z  = 1.0f / tzs;
        float inv_z2 = inv_z * inv_z;
        float J00 = FXC * inv_z, J02 = -FXC * txtz * inv_z2;
        float J11 = FYC * inv_z, J12 = -FYC * tytz * inv_z2;

        // Tm = J @ Wrot
        float Tm00 = J00*W00 + J02*W20;
        float Tm01 = J00*W01 + J02*W21;
        float Tm02 = J00*W02 + J02*W22;
        float Tm10 = J11*W10 + J12*W20;
        float Tm11 = J11*W11 + J12*W21;
        float Tm12 = J11*W12 + J12*W22;

        // cov = Tm Sigma Tm^T
        float v00 = S00*Tm00 + S01*Tm01 + S02*Tm02;
        float v01 = S01*Tm00 + S11*Tm01 + S12*Tm02;
        float v02 = S02*Tm00 + S12*Tm01 + S22*Tm02;
        float v10 = S00*Tm10 + S01*Tm11 + S02*Tm12;
        float v11 = S01*Tm10 + S11*Tm11 + S12*Tm12;
        float v12 = S02*Tm10 + S12*Tm11 + S22*Tm12;
        float cov00 = Tm00*v00 + Tm01*v01 + Tm02*v02;
        float cov01 = Tm10*v00 + Tm11*v01 + Tm12*v02;
        float cov11 = Tm10*v10 + Tm11*v11 + Tm12*v12;

        float det_orig = cov00*cov11 - cov01*cov01;
        float a = cov00 + 0.3f;
        float c = cov11 + 0.3f;
        float b = cov01;
        float det = a*c - b*b;
        visible = visible && (det > 0.0f);
        float dets = (det > 0.0f) ? det : 1.0f;
        float comp = sqrtf(fmaxf(det_orig / dets, 0.0f));

        float opac = 1.0f / (1.0f + __expf(-opacities[i]));
        op_eff = opac * comp * (visible ? 1.0f : 0.0f);

        float inv_det = 1.0f / dets;
        float conA = c * inv_det, conB = -b * inv_det, conC = a * inv_det;
        Ah = -0.5f * conA;
        Bh = -conB;
        Ch = -0.5f * conC;

        float mid = 0.5f * (a + c);
        float lam = mid + sqrtf(fmaxf(mid*mid - det, 0.1f));
        radii = visible ? (int)ceilf(3.0f * sqrtf(lam)) : 0;

        mx = FXC * tx / tzs + (IMG_W - 1) * 0.5f;
        my = FYC * ty / tzs + (IMG_H - 1) * 0.5f;

        cr = fmaxf(shs[3*i+0] * SH_C0 + 0.5f, 0.0f);
        cg = fmaxf(shs[3*i+1] * SH_C0 + 0.5f, 0.0f);
        cb = fmaxf(shs[3*i+2] * SH_C0 + 0.5f, 0.0f);

        // log-space alpha cutoff (0.01 margin covers __expf/__logf rounding;
        // the per-pixel tests remain exact/authoritative)
        if (op_eff > 0.0f) tpow = -__logf(255.0f * op_eff) - 0.01f;
        else               tpow = INF;

        // exact conic bbox half-extents of the {power >= tpow} region:
        // dx_max = sqrt(-2*tpow*a), dy_max = sqrt(-2*tpow*c)
        if (tpow < 0.0f) {
            ex = sqrtf(fmaxf(-2.0f * tpow * a, 0.0f)) + 1e-3f;
            ey = sqrtf(fmaxf(-2.0f * tpow * c, 0.0f)) + 1e-3f;
        }

        key = visible ? tz : INF;
    }

    // ---- stable rank sort (matches jnp.argsort stable semantics) ----
    __shared__ float keys[PMAX];
    keys[i] = key;
    __syncthreads();
    int rank = 0;
    float ki = key;
    for (int j = 0; j < PMAX; j++) {
        float kj = keys[j];
        rank += (kj < ki) || (kj == ki && j < i);
    }
    g_s0[rank] = make_float4(mx, my, Ah, Bh);
    g_s1[rank] = make_float4(Ch, op_eff, tpow, ex);
    g_s2[rank] = make_float4(cr, cg, cb, ey);

    // tail outputs: viewspace_points (zeros) and radii (original order)
    const int rgb_n = 3 * IMG_H * IMG_W;
    if (out_size >= rgb_n + 4 * PMAX) {
        d_out[rgb_n + 3*i + 0] = 0.0f;
        d_out[rgb_n + 3*i + 1] = 0.0f;
        d_out[rgb_n + 3*i + 2] = 0.0f;
        d_out[rgb_n + 3*PMAX + i] = (float)radii;
    }
}

__global__ void __launch_bounds__(256) raster_kernel(float* __restrict__ out)
{
    __shared__ float4 c0[PMAX];
    __shared__ float4 c1[PMAX];
    __shared__ float4 c2[PMAX];
    __shared__ int warp_cnt[8];
    __shared__ int s_n;

    int t = threadIdx.x;
    int lane = t & 31;
    int wid  = t >> 5;

    int tile_x0 = blockIdx.x * 16;
    int tile_y0 = blockIdx.y * 16;
    float bx0 = (float)tile_x0;
    float bx1 = (float)(tile_x0 + 15);
    float by0 = (float)tile_y0;
    float by1 = (float)(tile_y0 + 15);

    if (t == 0) s_n = 0;
    __syncthreads();

    // ---- order-preserving compaction: cull Gaussians against the tile bbox ----
    for (int r = 0; r < PMAX; r += 256) {
        int gid = r + t;
        float4 a = g_s0[gid];   // mx, my, A', B'
        float4 b = g_s1[gid];   // C', op, tpow, ex
        float4 c = g_s2[gid];   // cr, cg, cb, ey
        bool pred = (b.z < 0.0f)
                 && (a.x + b.w >= bx0) && (a.x - b.w <= bx1)
                 && (a.y + c.w >= by0) && (a.y - c.w <= by1);
        unsigned m = __ballot_sync(0xffffffffu, pred);
        if (lane == 0) warp_cnt[wid] = __popc(m);
        int wprefix = __popc(m & ((1u << lane) - 1u));
        __syncthreads();
        int base = s_n;
        int woff = 0;
        for (int w = 0; w < wid; w++) woff += warp_cnt[w];
        if (pred) {
            int pos = base + woff + wprefix;
            c0[pos] = a; c1[pos] = b; c2[pos] = c;
        }
        __syncthreads();
        if (t == 0) {
            int tot = 0;
            for (int w = 0; w < 8; w++) tot += warp_cnt[w];
            s_n = base + tot;
        }
        __syncthreads();
    }
    int n = s_n;

    // ---- per-pixel compositing over the culled, depth-ordered list ----
    int px = tile_x0 + (t & 15);
    int py = tile_y0 + (t >> 4);
    float fx = (float)px;
    float fy = (float)py;

    float T = 1.0f;
    float cr = 0.0f, cg = 0.0f, cb = 0.0f;

    for (int i = 0; i < n; i++) {
        float4 a = c0[i];
        float4 b = c1[i];
        float dx = fx - a.x;
        float dy = fy - a.y;
        // power = A'*dx^2 + C'*dy^2 + B'*dx*dy   (A'=-0.5A, C'=-0.5C, B'=-B)
        float power = fmaf(a.z, dx * dx, fmaf(b.x, dy * dy, a.w * dx * dy));
        if (power > 0.0f || power < b.z) continue;   // b.z = tpow cutoff
        float alpha = fminf(0.99f, b.y * __expf(power));
        if (alpha < 0.003921569f) continue;          // 1/255
        float w = alpha * T;
        float4 c = c2[i];
        cr = fmaf(w, c.x, cr);
        cg = fmaf(w, c.y, cg);
        cb = fmaf(w, c.z, cb);
        T *= (1.0f - alpha);
        if (T < 1e-4f) break;                        // Texcl monotone nonincreasing
    }

    int idx = py * IMG_W + px;
    out[idx]                     = cr;
    out[IMG_H * IMG_W + idx]     = cg;
    out[2 * IMG_H * IMG_W + idx] = cb;
}

extern "C" void kernel_launch(void* const* d_in, const int* in_sizes, int n_in,
                              void* d_out, int out_size)
{
    const float* points    = (const float*)d_in[0];
    const float* scales    = (const float*)d_in[1];
    const float* rots      = (const float*)d_in[2];
    const float* opacities = (const float*)d_in[3];
    const float* shs       = (const float*)d_in[4];
    const float* viewmat   = (const float*)d_in[5];
    float* out = (float*)d_out;

    int P = in_sizes[0] / 3;
    if (P > PMAX) P = PMAX;

    prep_sort_kernel<<<1, PMAX>>>(points, scales, rots, opacities, shs, viewmat,
                                  out, out_size, P);
    raster_kernel<<<dim3(IMG_W / 16, IMG_H / 16), 256>>>(out);
}

// round 13
// speedup vs baseline: 2.8582x; 1.4438x over previous
#include <cuda_runtime.h>
#include <cuda_bf16.h>
#include <math.h>

#define PMAX 512
#define IMG_H 256
#define IMG_W 256
#define TANFOV 0.5f
#define FXC (IMG_W / (2.0f * TANFOV))
#define FYC (IMG_H / (2.0f * TANFOV))
#define SH_C0 0.28209479177387814f

// ---- unsorted per-gaussian records (written by prep, gathered by sort) ----
__device__ float4 g_u0[PMAX];
__device__ float4 g_u1[PMAX];
__device__ float4 g_u2[PMAX];
__device__ float  g_key[PMAX];

// ---- sorted, packed for the raster loop ----
// s0: mx, my, -0.5*conA, -conB
// s1: -0.5*conC, op_eff, tpow, ex   (bbox half-extent in x)
// s2: cr, cg, cb, ey                (bbox half-extent in y)
__device__ float4 g_s0[PMAX];
__device__ float4 g_s1[PMAX];
__device__ float4 g_s2[PMAX];

__global__ void __launch_bounds__(128) prep_kernel(
    const float* __restrict__ points,
    const float* __restrict__ scales,
    const float* __restrict__ rots,
    const float* __restrict__ opacities,
    const float* __restrict__ shs,
    const float* __restrict__ vm,
    float* __restrict__ d_out, int out_size, int P)
{
    const float INF = __int_as_float(0x7f800000);
    int i = blockIdx.x * 128 + threadIdx.x;
    if (i >= PMAX) return;

    float mx = 0.f, my = 0.f, Ah = 0.f, Bh = 0.f, Ch = 0.f;
    float op_eff = 0.f, tpow = INF, ex = 0.f, ey = 0.f;
    float cr = 0.f, cg = 0.f, cb = 0.f;
    float key = INF;
    int   radii = 0;

    if (i < P) {
        // scales -> s = exp
        float s0 = __expf(scales[3*i+0]);
        float s1 = __expf(scales[3*i+1]);
        float s2 = __expf(scales[3*i+2]);

        // quat normalize -> R
        float qr = rots[4*i+0], qx = rots[4*i+1], qy = rots[4*i+2], qz = rots[4*i+3];
        float qn = rsqrtf(qr*qr + qx*qx + qy*qy + qz*qz);
        qr *= qn; qx *= qn; qy *= qn; qz *= qn;
        float R00 = 1.f - 2.f*(qy*qy + qz*qz), R01 = 2.f*(qx*qy - qr*qz), R02 = 2.f*(qx*qz + qr*qy);
        float R10 = 2.f*(qx*qy + qr*qz), R11 = 1.f - 2.f*(qx*qx + qz*qz), R12 = 2.f*(qy*qz - qr*qx);
        float R20 = 2.f*(qx*qz - qr*qy), R21 = 2.f*(qy*qz + qr*qx), R22 = 1.f - 2.f*(qx*qx + qy*qy);

        // M = R * diag(s)
        float M00 = R00*s0, M01 = R01*s1, M02 = R02*s2;
        float M10 = R10*s0, M11 = R11*s1, M12 = R12*s2;
        float M20 = R20*s0, M21 = R21*s1, M22 = R22*s2;

        // Sigma = M M^T
        float S00 = M00*M00 + M01*M01 + M02*M02;
        float S01 = M00*M10 + M01*M11 + M02*M12;
        float S02 = M00*M20 + M01*M21 + M02*M22;
        float S11 = M10*M10 + M11*M11 + M12*M12;
        float S12 = M10*M20 + M11*M21 + M12*M22;
        float S22 = M20*M20 + M21*M21 + M22*M22;

        float W00 = vm[0], W01 = vm[1], W02 = vm[2],  T0 = vm[3];
        float W10 = vm[4], W11 = vm[5], W12 = vm[6],  T1 = vm[7];
        float W20 = vm[8], W21 = vm[9], W22 = vm[10], T2 = vm[11];
        float px = points[3*i+0], py = points[3*i+1], pz = points[3*i+2];
        float tx = W00*px + W01*py + W02*pz + T0;
        float ty = W10*px + W11*py + W12*pz + T1;
        float tz = W20*px + W21*py + W22*pz + T2;

        bool visible = tz > 0.2f;
        float tzs = visible ? tz : 1.0f;

        const float lim = 1.3f * TANFOV;
        float txtz = fminf(fmaxf(tx/tzs, -lim), lim) * tzs;
        float tytz = fminf(fmaxf(ty/tzs, -lim), lim) * tzs;

        float inv_z  = 1.0f / tzs;
        float inv_z2 = inv_z * inv_z;
        float J00 = FXC * inv_z, J02 = -FXC * txtz * inv_z2;
        float J11 = FYC * inv_z, J12 = -FYC * tytz * inv_z2;

        // Tm = J @ Wrot
        float Tm00 = J00*W00 + J02*W20;
        float Tm01 = J00*W01 + J02*W21;
        float Tm02 = J00*W02 + J02*W22;
        float Tm10 = J11*W10 + J12*W20;
        float Tm11 = J11*W11 + J12*W21;
        float Tm12 = J11*W12 + J12*W22;

        // cov = Tm Sigma Tm^T
        float v00 = S00*Tm00 + S01*Tm01 + S02*Tm02;
        float v01 = S01*Tm00 + S11*Tm01 + S12*Tm02;
        float v02 = S02*Tm00 + S12*Tm01 + S22*Tm02;
        float v10 = S00*Tm10 + S01*Tm11 + S02*Tm12;
        float v11 = S01*Tm10 + S11*Tm11 + S12*Tm12;
        float v12 = S02*Tm10 + S12*Tm11 + S22*Tm12;
        float cov00 = Tm00*v00 + Tm01*v01 + Tm02*v02;
        float cov01 = Tm10*v00 + Tm11*v01 + Tm12*v02;
        float cov11 = Tm10*v10 + Tm11*v11 + Tm12*v12;

        float det_orig = cov00*cov11 - cov01*cov01;
        float a = cov00 + 0.3f;
        float c = cov11 + 0.3f;
        float b = cov01;
        float det = a*c - b*b;
        visible = visible && (det > 0.0f);
        float dets = (det > 0.0f) ? det : 1.0f;
        float comp = sqrtf(fmaxf(det_orig / dets, 0.0f));

        float opac = 1.0f / (1.0f + __expf(-opacities[i]));
        op_eff = opac * comp * (visible ? 1.0f : 0.0f);

        float inv_det = 1.0f / dets;
        float conA = c * inv_det, conB = -b * inv_det, conC = a * inv_det;
        Ah = -0.5f * conA;
        Bh = -conB;
        Ch = -0.5f * conC;

        float mid = 0.5f * (a + c);
        float lam = mid + sqrtf(fmaxf(mid*mid - det, 0.1f));
        radii = visible ? (int)ceilf(3.0f * sqrtf(lam)) : 0;

        mx = FXC * tx / tzs + (IMG_W - 1) * 0.5f;
        my = FYC * ty / tzs + (IMG_H - 1) * 0.5f;

        cr = fmaxf(shs[3*i+0] * SH_C0 + 0.5f, 0.0f);
        cg = fmaxf(shs[3*i+1] * SH_C0 + 0.5f, 0.0f);
        cb = fmaxf(shs[3*i+2] * SH_C0 + 0.5f, 0.0f);

        // log-space alpha cutoff (0.01 margin covers __expf/__logf rounding;
        // the per-pixel tests remain exact/authoritative)
        if (op_eff > 0.0f) tpow = -__logf(255.0f * op_eff) - 0.01f;
        else               tpow = INF;

        // exact conic bbox half-extents of the {power >= tpow} region:
        // dx_max = sqrt(-2*tpow*a), dy_max = sqrt(-2*tpow*c)
        if (tpow < 0.0f) {
            ex = sqrtf(fmaxf(-2.0f * tpow * a, 0.0f)) + 1e-3f;
            ey = sqrtf(fmaxf(-2.0f * tpow * c, 0.0f)) + 1e-3f;
        }

        key = visible ? tz : INF;
    }

    g_u0[i] = make_float4(mx, my, Ah, Bh);
    g_u1[i] = make_float4(Ch, op_eff, tpow, ex);
    g_u2[i] = make_float4(cr, cg, cb, ey);
    g_key[i] = key;

    // tail outputs: viewspace_points (zeros) and radii (original order)
    const int rgb_n = 3 * IMG_H * IMG_W;
    if (out_size >= rgb_n + 4 * PMAX) {
        d_out[rgb_n + 3*i + 0] = 0.0f;
        d_out[rgb_n + 3*i + 1] = 0.0f;
        d_out[rgb_n + 3*i + 2] = 0.0f;
        d_out[rgb_n + 3*PMAX + i] = (float)radii;
    }
}

// Stable rank sort (matches jnp.argsort stable semantics), 4 blocks x 128.
// Each block caches all 512 keys in smem; each thread ranks its own gaussian
// and scatters the unsorted record to the sorted slot.
__global__ void __launch_bounds__(128) sort_kernel()
{
    __shared__ float keys[PMAX];
    int t = threadIdx.x;
    // cooperative load: 128 threads x 4 keys (float4)
    ((float4*)keys)[t] = ((const float4*)g_key)[t];
    __syncthreads();

    int i = blockIdx.x * 128 + t;
    float ki = keys[i];
    int rank = 0;
    const float4* k4 = (const float4*)keys;
    #pragma unroll 4
    for (int j = 0; j < PMAX / 4; j++) {
        float4 kv = k4[j];
        int j4 = j * 4;
        rank += (kv.x < ki) || (kv.x == ki && (j4 + 0) < i);
        rank += (kv.y < ki) || (kv.y == ki && (j4 + 1) < i);
        rank += (kv.z < ki) || (kv.z == ki && (j4 + 2) < i);
        rank += (kv.w < ki) || (kv.w == ki && (j4 + 3) < i);
    }
    g_s0[rank] = g_u0[i];
    g_s1[rank] = g_u1[i];
    g_s2[rank] = g_u2[i];
}

__global__ void __launch_bounds__(256) raster_kernel(float* __restrict__ out)
{
    __shared__ float4 c0[PMAX];
    __shared__ float4 c1[PMAX];
    __shared__ float4 c2[PMAX];
    __shared__ int warp_cnt[8];
    __shared__ int s_n;

    int t = threadIdx.x;
    int lane = t & 31;
    int wid  = t >> 5;

    int tile_x0 = blockIdx.x * 16;
    int tile_y0 = blockIdx.y * 16;
    float bx0 = (float)tile_x0;
    float bx1 = (float)(tile_x0 + 15);
    float by0 = (float)tile_y0;
    float by1 = (float)(tile_y0 + 15);

    if (t == 0) s_n = 0;
    __syncthreads();

    // ---- order-preserving compaction: cull Gaussians against the tile bbox ----
    for (int r = 0; r < PMAX; r += 256) {
        int gid = r + t;
        float4 a = g_s0[gid];   // mx, my, A', B'
        float4 b = g_s1[gid];   // C', op, tpow, ex
        float4 c = g_s2[gid];   // cr, cg, cb, ey
        bool pred = (b.z < 0.0f)
                 && (a.x + b.w >= bx0) && (a.x - b.w <= bx1)
                 && (a.y + c.w >= by0) && (a.y - c.w <= by1);
        unsigned m = __ballot_sync(0xffffffffu, pred);
        if (lane == 0) warp_cnt[wid] = __popc(m);
        int wprefix = __popc(m & ((1u << lane) - 1u));
        __syncthreads();
        int base = s_n;
        int woff = 0;
        for (int w = 0; w < wid; w++) woff += warp_cnt[w];
        if (pred) {
            int pos = base + woff + wprefix;
            c0[pos] = a; c1[pos] = b; c2[pos] = c;
        }
        __syncthreads();
        if (t == 0) {
            int tot = 0;
            for (int w = 0; w < 8; w++) tot += warp_cnt[w];
            s_n = base + tot;
        }
        __syncthreads();
    }
    int n = s_n;

    // ---- per-pixel compositing over the culled, depth-ordered list ----
    int px = tile_x0 + (t & 15);
    int py = tile_y0 + (t >> 4);
    float fx = (float)px;
    float fy = (float)py;

    float T = 1.0f;
    float cr = 0.0f, cg = 0.0f, cb = 0.0f;

    for (int i = 0; i < n; i++) {
        float4 a = c0[i];
        float4 b = c1[i];
        float dx = fx - a.x;
        float dy = fy - a.y;
        // power = A'*dx^2 + C'*dy^2 + B'*dx*dy   (A'=-0.5A, C'=-0.5C, B'=-B)
        float power = fmaf(a.z, dx * dx, fmaf(b.x, dy * dy, a.w * dx * dy));
        if (power > 0.0f || power < b.z) continue;   // b.z = tpow cutoff
        float alpha = fminf(0.99f, b.y * __expf(power));
        if (alpha < 0.003921569f) continue;          // 1/255
        float w = alpha * T;
        float4 c = c2[i];
        cr = fmaf(w, c.x, cr);
        cg = fmaf(w, c.y, cg);
        cb = fmaf(w, c.z, cb);
        T *= (1.0f - alpha);
        if (T < 1e-4f) break;                        // Texcl monotone nonincreasing
    }

    int idx = py * IMG_W + px;
    out[idx]                     = cr;
    out[IMG_H * IMG_W + idx]     = cg;
    out[2 * IMG_H * IMG_W + idx] = cb;
}

extern "C" void kernel_launch(void* const* d_in, const int* in_sizes, int n_in,
                              void* d_out, int out_size)
{
    const float* points    = (const float*)d_in[0];
    const float* scales    = (const float*)d_in[1];
    const float* rots      = (const float*)d_in[2];
    const float* opacities = (const float*)d_in[3];
    const float* shs       = (const float*)d_in[4];
    const float* viewmat   = (const float*)d_in[5];
    float* out = (float*)d_out;

    int P = in_sizes[0] / 3;
    if (P > PMAX) P = PMAX;

    prep_kernel<<<4, 128>>>(points, scales, rots, opacities, shs, viewmat,
                            out, out_size, P);
    sort_kernel<<<4, 128>>>();
    raster_kernel<<<dim3(IMG_W / 16, IMG_H / 16), 256>>>(out);
}

// round 14
// speedup vs baseline: 3.8133x; 1.3342x over previous
#include <cuda_runtime.h>
#include <cuda_bf16.h>
#include <math.h>

#define PMAX 512
#define IMG_H 256
#define IMG_W 256
#define TANFOV 0.5f
#define FXC (IMG_W / (2.0f * TANFOV))
#define FYC (IMG_H / (2.0f * TANFOV))
#define SH_C0 0.28209479177387814f

// Single fused kernel: every 16x16-tile block redundantly computes the cheap
// per-Gaussian projection for all 512 Gaussians (2/thread), culls against its
// tile bbox (order-preserving compaction), rank-sorts only the survivors by
// depth, then composites. Block (0,0) also writes the radii/viewspace tail.
__global__ void __launch_bounds__(256) fused_kernel(
    const float* __restrict__ points,
    const float* __restrict__ scales,
    const float* __restrict__ rots,
    const float* __restrict__ opacities,
    const float* __restrict__ shs,
    const float* __restrict__ vm,
    float* __restrict__ out, int out_size, int P)
{
    // unsorted compacted records (tile-local survivors, original-index order)
    __shared__ float4 u0[PMAX];   // mx, my, -0.5A, -B
    __shared__ float4 u1[PMAX];   // -0.5C, op_eff, tpow, ex
    __shared__ float4 u2[PMAX];   // cr, cg, cb, ey
    __shared__ float  ukey[PMAX]; // depth key
    __shared__ short  sidx[PMAX]; // depth-sorted permutation of [0, n)
    __shared__ int    warp_cnt[8];
    __shared__ int    s_n;

    const float INF = __int_as_float(0x7f800000);
    int t = threadIdx.x;
    int lane = t & 31;
    int wid  = t >> 5;

    int tile_x0 = blockIdx.x * 16;
    int tile_y0 = blockIdx.y * 16;
    float bx0 = (float)tile_x0;
    float bx1 = (float)(tile_x0 + 15);
    float by0 = (float)tile_y0;
    float by1 = (float)(tile_y0 + 15);
    bool tail_block = (blockIdx.x | blockIdx.y) == 0;
    const int rgb_n = 3 * IMG_H * IMG_W;
    bool write_tail = tail_block && (out_size >= rgb_n + 4 * PMAX);

    // view matrix (broadcast loads, L2/const-hot)
    float W00 = vm[0], W01 = vm[1], W02 = vm[2],  T0 = vm[3];
    float W10 = vm[4], W11 = vm[5], W12 = vm[6],  T1 = vm[7];
    float W20 = vm[8], W21 = vm[9], W22 = vm[10], T2 = vm[11];

    if (t == 0) s_n = 0;
    __syncthreads();

    // ---- per-Gaussian prep + order-preserving tile compaction (2 rounds) ----
    for (int r = 0; r < PMAX; r += 256) {
        int i = r + t;

        float mx = 0.f, my = 0.f, Ah = 0.f, Bh = 0.f, Ch = 0.f;
        float op_eff = 0.f, tpow = INF, ex = 0.f, ey = 0.f;
        float cr = 0.f, cg = 0.f, cb = 0.f;
        float key = INF;
        int   radii = 0;

        if (i < P) {
            float s0 = __expf(scales[3*i+0]);
            float s1 = __expf(scales[3*i+1]);
            float s2 = __expf(scales[3*i+2]);

            float qr = rots[4*i+0], qx = rots[4*i+1], qy = rots[4*i+2], qz = rots[4*i+3];
            float qn = rsqrtf(qr*qr + qx*qx + qy*qy + qz*qz);
            qr *= qn; qx *= qn; qy *= qn; qz *= qn;
            float R00 = 1.f - 2.f*(qy*qy + qz*qz), R01 = 2.f*(qx*qy - qr*qz), R02 = 2.f*(qx*qz + qr*qy);
            float R10 = 2.f*(qx*qy + qr*qz), R11 = 1.f - 2.f*(qx*qx + qz*qz), R12 = 2.f*(qy*qz - qr*qx);
            float R20 = 2.f*(qx*qz - qr*qy), R21 = 2.f*(qy*qz + qr*qx), R22 = 1.f - 2.f*(qx*qx + qy*qy);

            float M00 = R00*s0, M01 = R01*s1, M02 = R02*s2;
            float M10 = R10*s0, M11 = R11*s1, M12 = R12*s2;
            float M20 = R20*s0, M21 = R21*s1, M22 = R22*s2;

            float S00 = M00*M00 + M01*M01 + M02*M02;
            float S01 = M00*M10 + M01*M11 + M02*M12;
            float S02 = M00*M20 + M01*M21 + M02*M22;
            float S11 = M10*M10 + M11*M11 + M12*M12;
            float S12 = M10*M20 + M11*M21 + M12*M22;
            float S22 = M20*M20 + M21*M21 + M22*M22;

            float px = points[3*i+0], py = points[3*i+1], pz = points[3*i+2];
            float tx = W00*px + W01*py + W02*pz + T0;
            float ty = W10*px + W11*py + W12*pz + T1;
            float tz = W20*px + W21*py + W22*pz + T2;

            bool visible = tz > 0.2f;
            float tzs = visible ? tz : 1.0f;

            const float lim = 1.3f * TANFOV;
            float txtz = fminf(fmaxf(tx/tzs, -lim), lim) * tzs;
            float tytz = fminf(fmaxf(ty/tzs, -lim), lim) * tzs;

            float inv_z  = 1.0f / tzs;
            float inv_z2 = inv_z * inv_z;
            float J00 = FXC * inv_z, J02 = -FXC * txtz * inv_z2;
            float J11 = FYC * inv_z, J12 = -FYC * tytz * inv_z2;

            float Tm00 = J00*W00 + J02*W20;
            float Tm01 = J00*W01 + J02*W21;
            float Tm02 = J00*W02 + J02*W22;
            float Tm10 = J11*W10 + J12*W20;
            float Tm11 = J11*W11 + J12*W21;
            float Tm12 = J11*W12 + J12*W22;

            float v00 = S00*Tm00 + S01*Tm01 + S02*Tm02;
            float v01 = S01*Tm00 + S11*Tm01 + S12*Tm02;
            float v02 = S02*Tm00 + S12*Tm01 + S22*Tm02;
            float v10 = S00*Tm10 + S01*Tm11 + S02*Tm12;
            float v11 = S01*Tm10 + S11*Tm11 + S12*Tm12;
            float v12 = S02*Tm10 + S12*Tm11 + S22*Tm12;
            float cov00 = Tm00*v00 + Tm01*v01 + Tm02*v02;
            float cov01 = Tm10*v00 + Tm11*v01 + Tm12*v02;
            float cov11 = Tm10*v10 + Tm11*v11 + Tm12*v12;

            float det_orig = cov00*cov11 - cov01*cov01;
            float a = cov00 + 0.3f;
            float c = cov11 + 0.3f;
            float b = cov01;
            float det = a*c - b*b;
            visible = visible && (det > 0.0f);
            float dets = (det > 0.0f) ? det : 1.0f;
            float comp = sqrtf(fmaxf(det_orig / dets, 0.0f));

            float opac = 1.0f / (1.0f + __expf(-opacities[i]));
            op_eff = opac * comp * (visible ? 1.0f : 0.0f);

            float inv_det = 1.0f / dets;
            Ah = -0.5f * (c * inv_det);
            Bh = b * inv_det;          // -conB = -(-b/det) = b/det
            Ch = -0.5f * (a * inv_det);

            float mid = 0.5f * (a + c);
            float lam = mid + sqrtf(fmaxf(mid*mid - det, 0.1f));
            radii = visible ? (int)ceilf(3.0f * sqrtf(lam)) : 0;

            mx = FXC * tx / tzs + (IMG_W - 1) * 0.5f;
            my = FYC * ty / tzs + (IMG_H - 1) * 0.5f;

            cr = fmaxf(shs[3*i+0] * SH_C0 + 0.5f, 0.0f);
            cg = fmaxf(shs[3*i+1] * SH_C0 + 0.5f, 0.0f);
            cb = fmaxf(shs[3*i+2] * SH_C0 + 0.5f, 0.0f);

            // log-space alpha cutoff (0.01 margin covers __expf/__logf rounding;
            // the per-pixel tests remain exact/authoritative)
            if (op_eff > 0.0f) tpow = -__logf(255.0f * op_eff) - 0.01f;
            else               tpow = INF;

            // exact conic bbox half-extents of the {power >= tpow} region
            if (tpow < 0.0f) {
                ex = sqrtf(fmaxf(-2.0f * tpow * a, 0.0f)) + 1e-3f;
                ey = sqrtf(fmaxf(-2.0f * tpow * c, 0.0f)) + 1e-3f;
            }

            key = visible ? tz : INF;
        }

        if (write_tail) {
            out[rgb_n + 3*i + 0] = 0.0f;
            out[rgb_n + 3*i + 1] = 0.0f;
            out[rgb_n + 3*i + 2] = 0.0f;
            out[rgb_n + 3*PMAX + i] = (float)radii;
        }

        bool pred = (tpow < 0.0f)
                 && (mx + ex >= bx0) && (mx - ex <= bx1)
                 && (my + ey >= by0) && (my - ey <= by1);
        unsigned m = __ballot_sync(0xffffffffu, pred);
        if (lane == 0) warp_cnt[wid] = __popc(m);
        int wprefix = __popc(m & ((1u << lane) - 1u));
        __syncthreads();
        int base = s_n;
        int woff = 0;
        for (int w = 0; w < wid; w++) woff += warp_cnt[w];
        if (pred) {
            int pos = base + woff + wprefix;
            u0[pos] = make_float4(mx, my, Ah, Bh);
            u1[pos] = make_float4(Ch, op_eff, tpow, ex);
            u2[pos] = make_float4(cr, cg, cb, ey);
            ukey[pos] = key;
        }
        __syncthreads();
        if (t == 0) {
            int tot = 0;
            for (int w = 0; w < 8; w++) tot += warp_cnt[w];
            s_n = base + tot;
        }
        __syncthreads();
    }
    int n = s_n;

    // ---- stable rank-sort of the survivors by depth ----
    // Compaction preserved original-index order, so tie-break by compacted
    // position reproduces jnp.argsort's stable semantics exactly.
    for (int e = t; e < n; e += 256) {
        float ke = ukey[e];
        int rank = 0;
        for (int j = 0; j < n; j++) {
            float kj = ukey[j];
            rank += (kj < ke) || (kj == ke && j < e);
        }
        sidx[rank] = (short)e;
    }
    __syncthreads();

    // ---- per-pixel compositing over the culled, depth-ordered list ----
    int px = tile_x0 + (t & 15);
    int py = tile_y0 + (t >> 4);
    float fx = (float)px;
    float fy = (float)py;

    float T = 1.0f;
    float cr = 0.0f, cg = 0.0f, cb = 0.0f;

    for (int i = 0; i < n; i++) {
        int j = sidx[i];
        float4 a = u0[j];
        float4 b = u1[j];
        float dx = fx - a.x;
        float dy = fy - a.y;
        // power = A'*dx^2 + C'*dy^2 + B'*dx*dy   (A'=-0.5A, C'=-0.5C, B'=-B)
        float power = fmaf(a.z, dx * dx, fmaf(b.x, dy * dy, a.w * dx * dy));
        if (power > 0.0f || power < b.z) continue;   // b.z = tpow cutoff
        float alpha = fminf(0.99f, b.y * __expf(power));
        if (alpha < 0.003921569f) continue;          // 1/255
        float w = alpha * T;
        float4 c = u2[j];
        cr = fmaf(w, c.x, cr);
        cg = fmaf(w, c.y, cg);
        cb = fmaf(w, c.z, cb);
        T *= (1.0f - alpha);
        if (T < 1e-4f) break;                        // Texcl monotone nonincreasing
    }

    int idx = py * IMG_W + px;
    out[idx]                     = cr;
    out[IMG_H * IMG_W + idx]     = cg;
    out[2 * IMG_H * IMG_W + idx] = cb;
}

extern "C" void kernel_launch(void* const* d_in, const int* in_sizes, int n_in,
                              void* d_out, int out_size)
{
    const float* points    = (const float*)d_in[0];
    const float* scales    = (const float*)d_in[1];
    const float* rots      = (const float*)d_in[2];
    const float* opacities = (const float*)d_in[3];
    const float* shs       = (const float*)d_in[4];
    const float* viewmat   = (const float*)d_in[5];
    float* out = (float*)d_out;

    int P = in_sizes[0] / 3;
    if (P > PMAX) P = PMAX;

    fused_kernel<<<dim3(IMG_W / 16, IMG_H / 16), 256>>>(
        points, scales, rots, opacities, shs, viewmat, out, out_size, P);
}